// round 5
// baseline (speedup 1.0000x reference)
#include <cuda_runtime.h>
#include <cstdint>
#include <cstddef>

// ---------------------------------------------------------------------------
// Problem dims (fixed)
// ---------------------------------------------------------------------------
#define BATCH 64
#define SEQ   2048
#define IND   256
#define UNITS 256
#define M_TOTAL (BATCH * SEQ)          // 131072

typedef unsigned long long ull;

// ---------------------------------------------------------------------------
// Device-global scratch (no runtime allocation allowed)
// ---------------------------------------------------------------------------
__device__ float  g_xf[(size_t)M_TOTAL * UNITS];    // 128 MB
__device__ float  g_xs[(size_t)M_TOTAL * UNITS];    // 128 MB
// Pair-interleaved recurrent weights:
//   g_wpack[(m*128 + p)*256 + u] = { U_m[2p][u], U_m[2p+1][u] },  m=0:U_f, 1:U_s
__device__ float2 g_wpack[2 * 128 * 256];           // 512 KB

// ---------------------------------------------------------------------------
// Packed f32x2 helpers
// ---------------------------------------------------------------------------
__device__ __forceinline__ void fma2(ull& d, ull a, ull b) {
    asm("fma.rn.f32x2 %0, %1, %2, %0;" : "+l"(d) : "l"(a), "l"(b));
}
__device__ __forceinline__ void add2(ull& d, ull a) {
    asm("add.rn.f32x2 %0, %0, %1;" : "+l"(d) : "l"(a));
}
__device__ __forceinline__ ull pack2(float x, float y) {
    ull r;
    asm("mov.b64 %0, {%1, %2};" : "=l"(r)
        : "r"(__float_as_uint(x)), "r"(__float_as_uint(y)));
    return r;
}
__device__ __forceinline__ float2 unpack2(ull v) {
    unsigned lo, hi;
    asm("mov.b64 {%0, %1}, %2;" : "=r"(lo), "=r"(hi) : "l"(v));
    return make_float2(__uint_as_float(lo), __uint_as_float(hi));
}

// ---------------------------------------------------------------------------
// Prep: repack U_f / U_s into pair-interleaved layout
// ---------------------------------------------------------------------------
__global__ void prep_wpack(const float* __restrict__ Uf,
                           const float* __restrict__ Us) {
    int idx = blockIdx.x * blockDim.x + threadIdx.x;   // 0 .. 65535
    int u = idx & 255;
    int p = (idx >> 8) & 127;
    int m = idx >> 15;
    const float* U = m ? Us : Uf;
    float2 v;
    v.x = U[(2 * p) * 256 + u];
    v.y = U[(2 * p + 1) * 256 + u];
    g_wpack[(size_t)(m * 128 + p) * 256 + u] = v;
}

// ---------------------------------------------------------------------------
// Phase 1: xf = X @ W_f + b_f ; xs = X @ W_s + b_s
// BM=128, BN=128, BK=16, 256 threads, 8x8 microtile via f32x2.
// A tile stored pre-duplicated ({a,a} as u64) so inner loop has no packs.
// blockIdx.y: 0 -> F cols[0,128), 1 -> F cols[128,256), 2/3 -> same for S.
// ---------------------------------------------------------------------------
#define BM 128
#define BN 128
#define BK 16

__global__ __launch_bounds__(256, 2)
void gemm_in(const float* __restrict__ X,
             const float* __restrict__ Wf, const float* __restrict__ bf,
             const float* __restrict__ Ws, const float* __restrict__ bs) {
    __shared__ ull   sA[BK][BM + 2];   // row stride 130*8=1040B (16B aligned)
    __shared__ float sB[BK][BN];

    const int tid = threadIdx.x;
    const int which = blockIdx.y;
    const float* W    = (which < 2) ? Wf : Ws;
    const float* bias = (which < 2) ? bf : bs;
    float*       out  = (which < 2) ? g_xf : g_xs;
    const int    n0   = (which & 1) * BN;
    const size_t m0   = (size_t)blockIdx.x * BM;

    const int tx = tid & 15;     // column group: cols [8*tx, 8*tx+8)
    const int ty = tid >> 4;     // row group:    rows [8*ty, 8*ty+8)

    ull acc[8][4];
#pragma unroll
    for (int i = 0; i < 8; i++)
#pragma unroll
        for (int j = 0; j < 4; j++) acc[i][j] = 0ull;

    for (int k0 = 0; k0 < IND; k0 += BK) {
        // --- load A tile (128 rows x 16 k), pre-duplicated into sA[k][m] ---
#pragma unroll
        for (int it = 0; it < 2; it++) {
            int s   = tid + it * 256;          // 512 float4 slots
            int row = s >> 2;
            int kq  = (s & 3) * 4;
            float4 v = *(const float4*)&X[(m0 + row) * IND + k0 + kq];
            sA[kq + 0][row] = pack2(v.x, v.x);
            sA[kq + 1][row] = pack2(v.y, v.y);
            sA[kq + 2][row] = pack2(v.z, v.z);
            sA[kq + 3][row] = pack2(v.w, v.w);
        }
        // --- load B tile (16 k x 128 n) ---
#pragma unroll
        for (int it = 0; it < 2; it++) {
            int s  = tid + it * 256;           // 512 float4 slots
            int kr = s >> 5;
            int nq = (s & 31) * 4;
            *(float4*)&sB[kr][nq] =
                *(const float4*)&W[(size_t)(k0 + kr) * UNITS + n0 + nq];
        }
        __syncthreads();

#pragma unroll
        for (int k = 0; k < BK; k++) {
            ull a[8];
#pragma unroll
            for (int i = 0; i < 8; i++) a[i] = sA[k][ty * 8 + i];
            const ull* b2 = (const ull*)&sB[k][tx * 8];
            ull b[4];
#pragma unroll
            for (int j = 0; j < 4; j++) b[j] = b2[j];
#pragma unroll
            for (int i = 0; i < 8; i++)
#pragma unroll
                for (int j = 0; j < 4; j++) fma2(acc[i][j], a[i], b[j]);
        }
        __syncthreads();
    }

    // --- epilogue: bias + store ---
    float bv[8];
#pragma unroll
    for (int j = 0; j < 8; j++) bv[j] = bias[n0 + tx * 8 + j];
#pragma unroll
    for (int i = 0; i < 8; i++) {
        size_t row = m0 + ty * 8 + i;
        float2 r0 = unpack2(acc[i][0]);
        float2 r1 = unpack2(acc[i][1]);
        float2 r2 = unpack2(acc[i][2]);
        float2 r3 = unpack2(acc[i][3]);
        float4 o0 = make_float4(r0.x + bv[0], r0.y + bv[1],
                                r1.x + bv[2], r1.y + bv[3]);
        float4 o1 = make_float4(r2.x + bv[4], r2.y + bv[5],
                                r3.x + bv[6], r3.y + bv[7]);
        *(float4*)&out[row * UNITS + n0 + tx * 8]     = o0;
        *(float4*)&out[row * UNITS + n0 + tx * 8 + 4] = o1;
    }
}

// ---------------------------------------------------------------------------
// Phase 2: the recurrence. One CTA per batch row, 256 threads (thread = unit).
// Weight k-pairs (p = k/2, 128 pairs):
//   p in [0,40)   -> registers (160 regs/thread, both matrices)
//   p in [40,90)  -> shared memory (2 x 100 KB, pair-of-pair interleaved)
//   p in [90,128) -> streamed from L2 each step (identical across CTAs)
// ---------------------------------------------------------------------------
#define P_RF 40
#define P_SM 50
#define P_L2 38
#define SMEM_W1   ((P_SM / 2) * 256 * 16)        // 102400 B per matrix
#define SMEM_PH2  (2 * SMEM_W1 + 2048)           // + sh(1KB) + sfh(1KB) = 206848

// One matvec: dot(vec, U[:,u]) with the 3-tier weight split.
// rW passed by reference-to-array so it stays register-resident after inlining.
__device__ __forceinline__ float matvec(const ulonglong2* __restrict__ v16,
                                        const ull (&rW)[2 * P_RF],
                                        const ulonglong2* __restrict__ sW,
                                        const ull* __restrict__ gL,
                                        int u) {
    ull a0 = 0, a1 = 0, a2 = 0, a3 = 0;
#pragma unroll
    for (int q = 0; q < P_RF / 2; q++) {
        ulonglong2 hv = v16[q];
        fma2(a0, hv.x, rW[2 * q]);
        fma2(a1, hv.y, rW[2 * q + 1]);
    }
#pragma unroll
    for (int q = 0; q < P_SM / 2; q++) {
        ulonglong2 hv = v16[P_RF / 2 + q];
        ulonglong2 wv = sW[q * 256 + u];
        fma2(a2, hv.x, wv.x);
        fma2(a3, hv.y, wv.y);
    }
#pragma unroll
    for (int q = 0; q < P_L2 / 2; q++) {
        ulonglong2 hv = v16[(P_RF + P_SM) / 2 + q];
        ull w0 = __ldcg(&gL[(size_t)(2 * q) * 256 + u]);
        ull w1 = __ldcg(&gL[(size_t)(2 * q + 1) * 256 + u]);
        fma2(a0, hv.x, w0);
        fma2(a1, hv.y, w1);
    }
    add2(a0, a1);
    add2(a2, a3);
    add2(a0, a2);
    float2 r = unpack2(a0);
    return r.x + r.y;
}

__global__ __launch_bounds__(256, 1)
void mgu_scan(float* __restrict__ out) {
    extern __shared__ char smem[];
    ulonglong2* sW4f = (ulonglong2*)(smem);
    ulonglong2* sW4s = (ulonglong2*)(smem + SMEM_W1);
    float* sh  = (float*)(smem + 2 * SMEM_W1);
    float* sfh = (float*)(smem + 2 * SMEM_W1 + 1024);

    const int tid = threadIdx.x;
    const int u   = tid;
    const int b   = blockIdx.x;

    const ull* wp = (const ull*)g_wpack;   // ull view: index (m*128+p)*256 + u

    // ---- register-resident weight pairs (fully unrolled -> stays in RF) ----
    ull rWf[2 * P_RF / 2 * 2];   // = rW arrays below
    (void)rWf;
    ull rF[2 * P_RF];  // NOTE: only first P_RF used per matrix; see below
    (void)rF;

    ull rWF[2 * P_RF];   // interleaving not needed; use two arrays:
    (void)rWF;

    // (clean declarations)
    ull regF[2 * P_RF];  // placeholder to silence; real arrays follow
    (void)regF;

    ull wf_r[2 * P_RF];  // final: wf_r holds U_f pairs, ws_r holds U_s pairs
    ull ws_r[2 * P_RF];
#pragma unroll
    for (int p = 0; p < P_RF; p++) {
        wf_r[p] = wp[(size_t)p * 256 + u];
        ws_r[p] = wp[(size_t)(128 + p) * 256 + u];
    }
#pragma unroll
    for (int p = P_RF; p < 2 * P_RF; p++) { wf_r[p] = 0ull; ws_r[p] = 0ull; }

    // ---- cooperative smem weight preload (pair-of-pair interleaved) ----
    for (int i = tid; i < (P_SM / 2) * 256; i += 256) {
        int q  = i >> 8;
        int uu = i & 255;
        int p  = P_RF + 2 * q;
        ulonglong2 vf, vs;
        vf.x = wp[(size_t)p * 256 + uu];
        vf.y = wp[(size_t)(p + 1) * 256 + uu];
        vs.x = wp[(size_t)(128 + p) * 256 + uu];
        vs.y = wp[(size_t)(128 + p + 1) * 256 + uu];
        sW4f[i] = vf;
        sW4s[i] = vs;
    }

    sh[u] = 0.0f;                 // h0 = 0
    float h_reg = 0.0f;
    __syncthreads();

    const ull* gLf = wp + (size_t)(P_RF + P_SM) * 256;          // U_f pairs 90..127
    const ull* gLs = wp + (size_t)(128 + P_RF + P_SM) * 256;    // U_s pairs 90..127

    size_t xoff = ((size_t)b * SEQ) * UNITS + u;

    for (int t = 0; t < SEQ; t++) {
        float xf_v = __ldcg(&g_xf[xoff]);
        float xs_v = __ldcg(&g_xs[xoff]);

        // ---- matvec 1: h @ U_f -> forget gate ----
        float dotf = matvec((const ulonglong2*)sh,
                            *(const ull(*)[2 * P_RF])wf_r, sW4f, gLf, u);
        float fpre = xf_v + dotf;
        float f = 1.0f / (1.0f + __expf(-fpre));     // safe: exp(inf)->0/1 limits
        sfh[u] = f * h_reg;
        __syncthreads();

        // ---- matvec 2: (f*h) @ U_s -> candidate ----
        float dots = matvec((const ulonglong2*)sfh,
                            *(const ull(*)[2 * P_RF])ws_r, sW4s, gLs, u);
        float spre = xs_v + dots;
        // overflow-safe tanh via exp(-2|x|)
        float ax = fabsf(spre);
        float e  = __expf(-2.0f * ax);
        float th = (1.0f - e) / (1.0f + e);
        th = copysignf(th, spre);

        float hn = h_reg + f * (th - h_reg);   // == (1-f)*h + f*th
        out[xoff] = hn;
        sh[u] = hn;
        h_reg = hn;
        xoff += UNITS;
        __syncthreads();
    }
}

// ---------------------------------------------------------------------------
// Entry point
// ---------------------------------------------------------------------------
extern "C" void kernel_launch(void* const* d_in, const int* in_sizes, int n_in,
                              void* d_out, int out_size) {
    const float* X  = (const float*)d_in[0];
    const float* Wf = (const float*)d_in[1];
    const float* Uf = (const float*)d_in[2];
    const float* bf = (const float*)d_in[3];
    const float* Ws = (const float*)d_in[4];
    const float* Us = (const float*)d_in[5];
    const float* bs = (const float*)d_in[6];
    float* out = (float*)d_out;
    (void)in_sizes; (void)n_in; (void)out_size;

    cudaFuncSetAttribute(mgu_scan,
                         cudaFuncAttributeMaxDynamicSharedMemorySize, SMEM_PH2);

    prep_wpack<<<256, 256>>>(Uf, Us);
    gemm_in<<<dim3(M_TOTAL / BM, 4), 256>>>(X, Wf, bf, Ws, bs);
    mgu_scan<<<BATCH, 256, SMEM_PH2>>>(out);
}

// round 6
// speedup vs baseline: 1.2227x; 1.2227x over previous
#include <cuda_runtime.h>
#include <cstdint>
#include <cstddef>

// ---------------------------------------------------------------------------
// Problem dims (fixed)
// ---------------------------------------------------------------------------
#define BATCH 64
#define SEQ   2048
#define IND   256
#define UNITS 256
#define M_TOTAL (BATCH * SEQ)          // 131072

typedef unsigned long long ull;

// ---------------------------------------------------------------------------
// Device-global scratch (no runtime allocation allowed)
// ---------------------------------------------------------------------------
__device__ float g_xf[(size_t)M_TOTAL * UNITS];    // 128 MB
__device__ float g_xs[(size_t)M_TOTAL * UNITS];    // 128 MB

// ---------------------------------------------------------------------------
// Packed f32x2 helpers
// ---------------------------------------------------------------------------
__device__ __forceinline__ void fma2(ull& d, ull a, ull b) {
    asm("fma.rn.f32x2 %0, %1, %2, %0;" : "+l"(d) : "l"(a), "l"(b));
}
__device__ __forceinline__ void add2(ull& d, ull a) {
    asm("add.rn.f32x2 %0, %0, %1;" : "+l"(d) : "l"(a));
}
__device__ __forceinline__ ull pack2(float x, float y) {
    ull r;
    asm("mov.b64 %0, {%1, %2};" : "=l"(r)
        : "r"(__float_as_uint(x)), "r"(__float_as_uint(y)));
    return r;
}
__device__ __forceinline__ float2 unpack2(ull v) {
    unsigned lo, hi;
    asm("mov.b64 {%0, %1}, %2;" : "=r"(lo), "=r"(hi) : "l"(v));
    return make_float2(__uint_as_float(lo), __uint_as_float(hi));
}

// ---------------------------------------------------------------------------
// Phase 1: xf = X @ W_f + b_f ; xs = X @ W_s + b_s   (unchanged, ~0.6ms)
// BM=128, BN=128, BK=16, 256 threads, 8x8 microtile via f32x2.
// A tile stored pre-duplicated ({a,a} as u64) so inner loop has no packs.
// blockIdx.y: 0 -> F cols[0,128), 1 -> F cols[128,256), 2/3 -> same for S.
// ---------------------------------------------------------------------------
#define BM 128
#define BN 128
#define BK 16

__global__ __launch_bounds__(256, 2)
void gemm_in(const float* __restrict__ X,
             const float* __restrict__ Wf, const float* __restrict__ bf,
             const float* __restrict__ Ws, const float* __restrict__ bs) {
    __shared__ ull   sA[BK][BM + 2];
    __shared__ float sB[BK][BN];

    const int tid = threadIdx.x;
    const int which = blockIdx.y;
    const float* W    = (which < 2) ? Wf : Ws;
    const float* bias = (which < 2) ? bf : bs;
    float*       out  = (which < 2) ? g_xf : g_xs;
    const int    n0   = (which & 1) * BN;
    const size_t m0   = (size_t)blockIdx.x * BM;

    const int tx = tid & 15;
    const int ty = tid >> 4;

    ull acc[8][4];
#pragma unroll
    for (int i = 0; i < 8; i++)
#pragma unroll
        for (int j = 0; j < 4; j++) acc[i][j] = 0ull;

    for (int k0 = 0; k0 < IND; k0 += BK) {
#pragma unroll
        for (int it = 0; it < 2; it++) {
            int s   = tid + it * 256;
            int row = s >> 2;
            int kq  = (s & 3) * 4;
            float4 v = *(const float4*)&X[(m0 + row) * IND + k0 + kq];
            sA[kq + 0][row] = pack2(v.x, v.x);
            sA[kq + 1][row] = pack2(v.y, v.y);
            sA[kq + 2][row] = pack2(v.z, v.z);
            sA[kq + 3][row] = pack2(v.w, v.w);
        }
#pragma unroll
        for (int it = 0; it < 2; it++) {
            int s  = tid + it * 256;
            int kr = s >> 5;
            int nq = (s & 31) * 4;
            *(float4*)&sB[kr][nq] =
                *(const float4*)&W[(size_t)(k0 + kr) * UNITS + n0 + nq];
        }
        __syncthreads();

#pragma unroll
        for (int k = 0; k < BK; k++) {
            ull a[8];
#pragma unroll
            for (int i = 0; i < 8; i++) a[i] = sA[k][ty * 8 + i];
            const ull* b2 = (const ull*)&sB[k][tx * 8];
            ull b[4];
#pragma unroll
            for (int j = 0; j < 4; j++) b[j] = b2[j];
#pragma unroll
            for (int i = 0; i < 8; i++)
#pragma unroll
                for (int j = 0; j < 4; j++) fma2(acc[i][j], a[i], b[j]);
        }
        __syncthreads();
    }

    float bv[8];
#pragma unroll
    for (int j = 0; j < 8; j++) bv[j] = bias[n0 + tx * 8 + j];
#pragma unroll
    for (int i = 0; i < 8; i++) {
        size_t row = m0 + ty * 8 + i;
        float2 r0 = unpack2(acc[i][0]);
        float2 r1 = unpack2(acc[i][1]);
        float2 r2 = unpack2(acc[i][2]);
        float2 r3 = unpack2(acc[i][3]);
        float4 o0 = make_float4(r0.x + bv[0], r0.y + bv[1],
                                r1.x + bv[2], r1.y + bv[3]);
        float4 o1 = make_float4(r2.x + bv[4], r2.y + bv[5],
                                r3.x + bv[6], r3.y + bv[7]);
        *(float4*)&out[row * UNITS + n0 + tx * 8]     = o0;
        *(float4*)&out[row * UNITS + n0 + tx * 8 + 4] = o1;
    }
}

// ---------------------------------------------------------------------------
// Phase 2: cluster-2 recurrence.
// 128 CTAs (cluster of 2 per batch row). CTA rank r owns units [r*128,r*128+128).
// 256 threads: half = t>>7 selects k-range [half*128, half*128+128),
// uLocal = t&127 selects the unit. Thread weights: 64 k-pairs per matrix:
// 40 pairs in registers, 24 pairs in smem. Partner partials combined via smem.
// Cross-CTA exchange of the 128-wide fh / h slices via DSMEM stores +
// cluster barrier (x2 per step).
// ---------------------------------------------------------------------------
#define P_RF 40                       // register pairs per matrix per thread
#define SW_J 12                       // smem ulonglong2 slots (= 24 pairs)
#define SW_U2 (SW_J * 256)            // ulonglong2 per matrix
#define SMEM_SCAN (2 * SW_U2 * 16 + 3 * 256 * 4)   // 98304 + 3072 = 101376

__device__ __forceinline__ uint32_t ctarank() {
    uint32_t r;
    asm("mov.u32 %0, %%cluster_ctarank;" : "=r"(r));
    return r;
}
__device__ __forceinline__ void st_peer_f32(const float* laddr, uint32_t peer, float v) {
    uint32_t la = (uint32_t)__cvta_generic_to_shared(laddr);
    uint32_t ra;
    asm volatile("mapa.shared::cluster.u32 %0, %1, %2;" : "=r"(ra) : "r"(la), "r"(peer));
    asm volatile("st.shared::cluster.f32 [%0], %1;" :: "r"(ra), "f"(v) : "memory");
}
#define CLU_ARRIVE() asm volatile("barrier.cluster.arrive.aligned;" ::: "memory")
#define CLU_WAIT()   asm volatile("barrier.cluster.wait.aligned;"   ::: "memory")

// Partial dot over this thread's 128-wide k-half.
// vh: 32 ulonglong2 (broadcast within warp). rW: 40 RF pairs. sW: smem tier.
__device__ __forceinline__ float matvec_half(const ulonglong2* __restrict__ vh,
                                             const ull (&rW)[P_RF],
                                             const ulonglong2* __restrict__ sW,
                                             int t) {
    ull a0 = 0, a1 = 0, a2 = 0, a3 = 0;
#pragma unroll
    for (int j = 0; j < 20; j++) {              // pairs 0..39 (RF)
        ulonglong2 hv = vh[j];
        fma2(a0, hv.x, rW[2 * j]);
        fma2(a1, hv.y, rW[2 * j + 1]);
    }
#pragma unroll
    for (int j = 0; j < SW_J; j++) {            // pairs 40..63 (smem)
        ulonglong2 hv = vh[20 + j];
        ulonglong2 wv = sW[j * 256 + t];
        fma2(a2, hv.x, wv.x);
        fma2(a3, hv.y, wv.y);
    }
    add2(a0, a1);
    add2(a2, a3);
    add2(a0, a2);
    float2 r = unpack2(a0);
    return r.x + r.y;
}

__global__ __launch_bounds__(256, 1) __cluster_dims__(2, 1, 1)
void mgu_scan(const float* __restrict__ Uf, const float* __restrict__ Us,
              float* __restrict__ out) {
    extern __shared__ char smem[];
    ulonglong2* sWf = (ulonglong2*)smem;
    ulonglong2* sWs = sWf + SW_U2;
    float* sh  = (float*)(sWs + SW_U2);   // full 256-unit h vector
    float* sfh = sh + 256;                // full 256-unit f*h vector
    float* sP  = sfh + 256;               // per-thread partials

    const int t     = threadIdx.x;
    const int half  = t >> 7;
    const int uL    = t & 127;
    const uint32_t rank = ctarank();
    const uint32_t peer = rank ^ 1u;
    const int ug    = (int)rank * 128 + uL;   // global unit this thread serves
    const int b     = blockIdx.x >> 1;        // batch row (cluster id)
    const int k0    = half * 128;             // this thread's k-range base

    // ---- RF weight preload: pairs p<40 -> k in [k0, k0+80) ----
    ull rF[P_RF], rS[P_RF];
#pragma unroll
    for (int p = 0; p < P_RF; p++) {
        rF[p] = pack2(Uf[(size_t)(k0 + 2 * p)     * UNITS + ug],
                      Uf[(size_t)(k0 + 2 * p + 1) * UNITS + ug]);
        rS[p] = pack2(Us[(size_t)(k0 + 2 * p)     * UNITS + ug],
                      Us[(size_t)(k0 + 2 * p + 1) * UNITS + ug]);
    }
    // ---- smem weight preload: k in [k0+80, k0+128), own column ----
#pragma unroll
    for (int j = 0; j < SW_J; j++) {
        int kk = k0 + 80 + 4 * j;
        sWf[j * 256 + t] = make_ulonglong2(
            pack2(Uf[(size_t)kk       * UNITS + ug], Uf[(size_t)(kk + 1) * UNITS + ug]),
            pack2(Uf[(size_t)(kk + 2) * UNITS + ug], Uf[(size_t)(kk + 3) * UNITS + ug]));
        sWs[j * 256 + t] = make_ulonglong2(
            pack2(Us[(size_t)kk       * UNITS + ug], Us[(size_t)(kk + 1) * UNITS + ug]),
            pack2(Us[(size_t)(kk + 2) * UNITS + ug], Us[(size_t)(kk + 3) * UNITS + ug]));
    }
    sh[t] = 0.0f;                 // h0 = 0 (full local copy of all 256 units)
    float h_reg = 0.0f;           // owners (t<128) track h of unit ug
    float f_reg = 0.0f;
    __syncthreads();
    CLU_ARRIVE(); CLU_WAIT();     // both CTAs fully initialized

    const ulonglong2* vh_h  = (const ulonglong2*)sh  + half * 32;
    const ulonglong2* vh_fh = (const ulonglong2*)sfh + half * 32;

    size_t xoff = ((size_t)b * SEQ) * UNITS + ug;

    for (int step = 0; step < SEQ; step++) {
        float xf_v = 0.0f, xs_v = 0.0f;
        if (t < 128) {                        // owners prefetch this step's x
            xf_v = __ldcg(&g_xf[xoff]);
            xs_v = __ldcg(&g_xs[xoff]);
        }

        // ---- matvec 1: h @ U_f (k-half partial) ----
        float p1 = matvec_half(vh_h, rF, sWf, t);
        sP[t] = p1;
        __syncthreads();

        if (t < 128) {
            float pre = xf_v + sP[t] + sP[t + 128];
            f_reg = 1.0f / (1.0f + __expf(-pre));
            float fh = f_reg * h_reg;
            sfh[ug] = fh;
            st_peer_f32(&sfh[ug], peer, fh);
        }
        CLU_ARRIVE(); CLU_WAIT();             // fh slices exchanged

        // ---- matvec 2: (f*h) @ U_s (k-half partial) ----
        float p2 = matvec_half(vh_fh, rS, sWs, t);
        sP[t] = p2;
        __syncthreads();

        if (t < 128) {
            float pre = xs_v + sP[t] + sP[t + 128];
            float ax = fabsf(pre);
            float e  = __expf(-2.0f * ax);
            float th = (1.0f - e) / (1.0f + e);    // overflow-safe tanh
            th = copysignf(th, pre);
            float hn = h_reg + f_reg * (th - h_reg);   // (1-f)h + f*th
            out[xoff] = hn;
            sh[ug] = hn;
            st_peer_f32(&sh[ug], peer, hn);
            h_reg = hn;
        }
        xoff += UNITS;
        CLU_ARRIVE(); CLU_WAIT();             // h slices exchanged
    }
}

// ---------------------------------------------------------------------------
// Entry point (2 launches per invocation)
// ---------------------------------------------------------------------------
extern "C" void kernel_launch(void* const* d_in, const int* in_sizes, int n_in,
                              void* d_out, int out_size) {
    const float* X  = (const float*)d_in[0];
    const float* Wf = (const float*)d_in[1];
    const float* Uf = (const float*)d_in[2];
    const float* bf = (const float*)d_in[3];
    const float* Ws = (const float*)d_in[4];
    const float* Us = (const float*)d_in[5];
    const float* bs = (const float*)d_in[6];
    float* out = (float*)d_out;
    (void)in_sizes; (void)n_in; (void)out_size;

    cudaFuncSetAttribute(mgu_scan,
                         cudaFuncAttributeMaxDynamicSharedMemorySize, SMEM_SCAN);

    gemm_in<<<dim3(M_TOTAL / BM, 4), 256>>>(X, Wf, bf, Ws, bs);
    mgu_scan<<<2 * BATCH, 256, SMEM_SCAN>>>(Uf, Us, out);
}